// round 4
// baseline (speedup 1.0000x reference)
#include <cuda_runtime.h>
#include <math.h>

#define NN 100000
#define EE 1600000
#define ETOT (EE + NN)
#define DIM 128
#define HID 16
#define HEADS 4
#define F1 (HEADS * HID)   // 64
#define NEG 0.2f

#define SCAN_BLK 512
#define NBLK ((NN + SCAN_BLK - 1) / SCAN_BLK)   // 196

// ---------------- scratch (static device globals; no allocation) -------------
__device__ __align__(16) float g_h1[NN * F1];     // layer-1 transformed features
__device__ __align__(16) float g_as1[NN * HEADS];
__device__ __align__(16) float g_ad1[NN * HEADS];
__device__ __align__(16) float g_h3[NN * 2];      // layer-2 transformed features
__device__ float g_as2[NN];
__device__ float g_ad2[NN];

__device__ int g_deg[NN];
__device__ int g_offs[NN];
__device__ int g_cur[NN];
__device__ int g_bsum[256];
__device__ int g_bpre[256];
__device__ int g_csr_src[ETOT];

// ---------------- helpers ----------------------------------------------------
__device__ __forceinline__ void load_edge(const int* __restrict__ ei, int e,
                                          int& s, int& d) {
    if (e < EE) { s = ei[e]; d = ei[EE + e]; }
    else        { s = e - EE; d = e - EE; }   // self loops appended
}

__device__ __forceinline__ float lrelu(float v) {
    return v > 0.0f ? v : NEG * v;
}

// ---------------- kernels ----------------------------------------------------

// h1 = x @ W1 ;  alpha_s1/alpha_d1 per (node, head); also zeroes g_deg
__global__ __launch_bounds__(256) void k_gemm1(
    const float* __restrict__ x, const float* __restrict__ W1,
    const float* __restrict__ asrc, const float* __restrict__ adst) {

    __shared__ float4 Ws[DIM * F1 / 4];   // 32KB
    int tid = threadIdx.x;
    #pragma unroll
    for (int i = tid; i < DIM * F1 / 4; i += 256)
        Ws[i] = ((const float4*)W1)[i];

    // fused init: zero degree counters for this block's 32 nodes
    if (tid < 32) g_deg[blockIdx.x * 32 + tid] = 0;
    __syncthreads();

    int nodeLocal = tid >> 3;     // 0..31
    int tj = tid & 7;             // channels [tj*8, tj*8+8)
    int n = blockIdx.x * 32 + nodeLocal;
    const float* xr = x + (size_t)n * DIM;

    float4 a0 = make_float4(0.f, 0.f, 0.f, 0.f);
    float4 a1 = make_float4(0.f, 0.f, 0.f, 0.f);
    #pragma unroll 4
    for (int k = 0; k < DIM; k++) {
        float xv = __ldg(xr + k);
        float4 w0 = Ws[k * 16 + tj * 2];
        float4 w1 = Ws[k * 16 + tj * 2 + 1];
        a0.x += xv * w0.x; a0.y += xv * w0.y; a0.z += xv * w0.z; a0.w += xv * w0.w;
        a1.x += xv * w1.x; a1.y += xv * w1.y; a1.z += xv * w1.z; a1.w += xv * w1.w;
    }

    float4* h1p = (float4*)(g_h1 + (size_t)n * F1 + tj * 8);
    h1p[0] = a0; h1p[1] = a1;

    int j0 = tj * 8;
    float ps = a0.x * asrc[j0]     + a0.y * asrc[j0 + 1] +
               a0.z * asrc[j0 + 2] + a0.w * asrc[j0 + 3] +
               a1.x * asrc[j0 + 4] + a1.y * asrc[j0 + 5] +
               a1.z * asrc[j0 + 6] + a1.w * asrc[j0 + 7];
    float pd = a0.x * adst[j0]     + a0.y * adst[j0 + 1] +
               a0.z * adst[j0 + 2] + a0.w * adst[j0 + 3] +
               a1.x * adst[j0 + 4] + a1.y * adst[j0 + 5] +
               a1.z * adst[j0 + 6] + a1.w * adst[j0 + 7];
    ps += __shfl_xor_sync(0xffffffffu, ps, 1);
    pd += __shfl_xor_sync(0xffffffffu, pd, 1);
    if ((tj & 1) == 0) {
        int h = tj >> 1;
        g_as1[n * HEADS + h] = ps;
        g_ad1[n * HEADS + h] = pd;
    }
}

// ---------------- CSR build ---------------------------------------------------
__global__ void k_count(const int* __restrict__ ei) {
    int e = blockIdx.x * blockDim.x + threadIdx.x;
    if (e >= ETOT) return;
    int s, d; load_edge(ei, e, s, d);
    atomicAdd(&g_deg[d], 1);
}

__global__ __launch_bounds__(SCAN_BLK) void k_scan1() {
    __shared__ int sh[SCAN_BLK];
    int t = threadIdx.x;
    int i = blockIdx.x * SCAN_BLK + t;
    int v = (i < NN) ? g_deg[i] : 0;
    sh[t] = v;
    __syncthreads();
    #pragma unroll
    for (int off = 1; off < SCAN_BLK; off <<= 1) {
        int add = (t >= off) ? sh[t - off] : 0;
        __syncthreads();
        sh[t] += add;
        __syncthreads();
    }
    if (i < NN) g_offs[i] = sh[t] - v;   // exclusive
    if (t == SCAN_BLK - 1) g_bsum[blockIdx.x] = sh[t];
}

__global__ __launch_bounds__(256) void k_scan2() {
    __shared__ int sh[256];
    int t = threadIdx.x;
    int v = (t < NBLK) ? g_bsum[t] : 0;
    sh[t] = v;
    __syncthreads();
    #pragma unroll
    for (int off = 1; off < 256; off <<= 1) {
        int add = (t >= off) ? sh[t - off] : 0;
        __syncthreads();
        sh[t] += add;
        __syncthreads();
    }
    if (t < NBLK) g_bpre[t] = sh[t] - v;  // exclusive
}

__global__ void k_scan3() {
    int i = blockIdx.x * blockDim.x + threadIdx.x;
    if (i >= NN) return;
    int o = g_offs[i] + g_bpre[i / SCAN_BLK];
    g_offs[i] = o;
    g_cur[i] = o;
}

__global__ void k_scatter(const int* __restrict__ ei) {
    int e = blockIdx.x * blockDim.x + threadIdx.x;
    if (e >= ETOT) return;
    int s, d; load_edge(ei, e, s, d);
    int pos = atomicAdd(&g_cur[d], 1);
    g_csr_src[pos] = s;
}

// ---------------- layer-1 aggregation (atomic-free) + fused l2prep ------------
// One warp per dst node. Lane owns channels (2*lane, 2*lane+1); head = lane>>3.
// Edge loop unrolled x4 for MLP.
__global__ __launch_bounds__(256) void k_agg1(
    const float* __restrict__ b1, const float* __restrict__ W2,
    const float* __restrict__ as2, const float* __restrict__ ad2) {

    int lane = threadIdx.x & 31;
    int n = blockIdx.x * 8 + (threadIdx.x >> 5);
    if (n >= NN) return;

    int h = lane >> 3;
    float adh = g_ad1[n * 4 + h];
    int start = g_offs[n];
    int end = start + g_deg[n];
    int c = 2 * lane;

    float acc0 = 0.f, acc1 = 0.f, wsum = 0.f;
    int i = start;
    for (; i + 4 <= end; i += 4) {
        int s0 = __ldg(g_csr_src + i + 0);
        int s1 = __ldg(g_csr_src + i + 1);
        int s2 = __ldg(g_csr_src + i + 2);
        int s3 = __ldg(g_csr_src + i + 3);
        float e0 = __ldg(g_as1 + s0 * 4 + h);
        float e1 = __ldg(g_as1 + s1 * 4 + h);
        float e2 = __ldg(g_as1 + s2 * 4 + h);
        float e3 = __ldg(g_as1 + s3 * 4 + h);
        float2 q0 = *(const float2*)(g_h1 + (size_t)s0 * F1 + c);
        float2 q1 = *(const float2*)(g_h1 + (size_t)s1 * F1 + c);
        float2 q2 = *(const float2*)(g_h1 + (size_t)s2 * F1 + c);
        float2 q3 = *(const float2*)(g_h1 + (size_t)s3 * F1 + c);
        float w0 = __expf(lrelu(e0 + adh));
        float w1 = __expf(lrelu(e1 + adh));
        float w2 = __expf(lrelu(e2 + adh));
        float w3 = __expf(lrelu(e3 + adh));
        acc0 += w0 * q0.x + w1 * q1.x;
        acc1 += w0 * q0.y + w1 * q1.y;
        acc0 += w2 * q2.x + w3 * q3.x;
        acc1 += w2 * q2.y + w3 * q3.y;
        wsum += (w0 + w1) + (w2 + w3);
    }
    for (; i < end; i++) {
        int s = __ldg(g_csr_src + i);
        float as = __ldg(g_as1 + s * 4 + h);
        float w = __expf(lrelu(as + adh));
        float2 hv = *(const float2*)(g_h1 + (size_t)s * F1 + c);
        acc0 += w * hv.x;
        acc1 += w * hv.y;
        wsum += w;
    }

    float inv = 1.0f / (wsum + 1e-16f);
    int c0 = c, c1 = c + 1;
    float v0 = acc0 * inv + b1[c0];
    float v1 = acc1 * inv + b1[c1];
    v0 = v0 > 0.f ? v0 : expm1f(v0);          // ELU
    v1 = v1 > 0.f ? v1 : expm1f(v1);

    float p0 = v0 * W2[c0 * 2 + 0] + v1 * W2[c1 * 2 + 0];
    float p1 = v0 * W2[c0 * 2 + 1] + v1 * W2[c1 * 2 + 1];
    #pragma unroll
    for (int o = 16; o > 0; o >>= 1) {
        p0 += __shfl_down_sync(0xffffffffu, p0, o);
        p1 += __shfl_down_sync(0xffffffffu, p1, o);
    }
    if (lane == 0) {
        g_h3[n * 2 + 0] = p0;
        g_h3[n * 2 + 1] = p1;
        g_as2[n] = p0 * as2[0] + p1 * as2[1];
        g_ad2[n] = p0 * ad2[0] + p1 * ad2[1];
    }
}

// ---------------- layer-2 aggregation (atomic-free) + output ------------------
// One warp per dst node; lanes stride over incident edges.
__global__ __launch_bounds__(256) void k_agg2(
    float* __restrict__ out, const float* __restrict__ b2) {

    int lane = threadIdx.x & 31;
    int n = blockIdx.x * 8 + (threadIdx.x >> 5);
    if (n >= NN) return;

    float ad = g_ad2[n];
    int start = g_offs[n];
    int end = start + g_deg[n];

    float a0 = 0.f, a1 = 0.f, wsum = 0.f;
    for (int i = start + lane; i < end; i += 32) {
        int s = __ldg(g_csr_src + i);
        float w = __expf(lrelu(__ldg(g_as2 + s) + ad));
        float2 hv = *(const float2*)(g_h3 + s * 2);
        a0 += w * hv.x;
        a1 += w * hv.y;
        wsum += w;
    }
    #pragma unroll
    for (int o = 16; o > 0; o >>= 1) {
        a0   += __shfl_down_sync(0xffffffffu, a0, o);
        a1   += __shfl_down_sync(0xffffffffu, a1, o);
        wsum += __shfl_down_sync(0xffffffffu, wsum, o);
    }
    if (lane == 0) {
        float inv = 1.0f / (wsum + 1e-16f);
        out[n * 2 + 0] = a0 * inv + b2[0];
        out[n * 2 + 1] = a1 * inv + b2[1];
    }
}

// ---------------- launch ------------------------------------------------------
extern "C" void kernel_launch(void* const* d_in, const int* in_sizes, int n_in,
                              void* d_out, int out_size) {
    const float* x    = (const float*)d_in[0];
    const int*   ei   = (const int*)  d_in[1];
    const float* W1   = (const float*)d_in[2];
    const float* as1  = (const float*)d_in[3];
    const float* ad1  = (const float*)d_in[4];
    const float* b1   = (const float*)d_in[5];
    const float* W2   = (const float*)d_in[6];
    const float* as2  = (const float*)d_in[7];
    const float* ad2  = (const float*)d_in[8];
    const float* b2   = (const float*)d_in[9];
    float* out = (float*)d_out;

    const int T = 256;
    k_gemm1<<<NN / 32, T>>>(x, W1, as1, ad1);
    k_count<<<(ETOT + T - 1) / T, T>>>(ei);
    k_scan1<<<NBLK, SCAN_BLK>>>();
    k_scan2<<<1, 256>>>();
    k_scan3<<<(NN + T - 1) / T, T>>>();
    k_scatter<<<(ETOT + T - 1) / T, T>>>(ei);
    k_agg1<<<(NN + 7) / 8, T>>>(b1, W2, as2, ad2);
    k_agg2<<<(NN + 7) / 8, T>>>(out, b2);
}

// round 5
// speedup vs baseline: 1.0328x; 1.0328x over previous
#include <cuda_runtime.h>
#include <math.h>

#define NN 100000
#define EE 1600000
#define ETOT (EE + NN)
#define DIM 128
#define HID 16
#define HEADS 4
#define F1 (HEADS * HID)   // 64
#define NEG 0.2f

#define SCAN_BLK 512
#define NBLK ((NN + SCAN_BLK - 1) / SCAN_BLK)   // 196

// ---------------- scratch (static device globals; no allocation) -------------
__device__ __align__(16) float g_h1[NN * F1];     // layer-1 transformed features
__device__ __align__(16) float g_as1[NN * HEADS];
__device__ __align__(16) float g_ad1[NN * HEADS];
__device__ __align__(16) float g_h3[NN * 2];      // layer-2 transformed features
__device__ float g_as2[NN];
__device__ float g_ad2[NN];

__device__ int g_deg[NN];
__device__ int g_offs[NN];
__device__ int g_cur[NN];
__device__ int g_bsum[256];
__device__ int g_bpre[256];
__device__ int g_csr_src[ETOT];

// ---------------- helpers ----------------------------------------------------
__device__ __forceinline__ void load_edge(const int* __restrict__ ei, int e,
                                          int& s, int& d) {
    if (e < EE) { s = ei[e]; d = ei[EE + e]; }
    else        { s = e - EE; d = e - EE; }   // self loops appended
}

__device__ __forceinline__ float lrelu(float v) {
    return v > 0.0f ? v : NEG * v;
}

// ---------------- kernels ----------------------------------------------------

__global__ void k_init() {
    int i = blockIdx.x * blockDim.x + threadIdx.x;
    if (i < NN) g_deg[i] = 0;
}

// h1 = x @ W1 ;  alpha_s1/alpha_d1 per (node, head)
__global__ __launch_bounds__(256) void k_gemm1(
    const float* __restrict__ x, const float* __restrict__ W1,
    const float* __restrict__ asrc, const float* __restrict__ adst) {

    __shared__ float4 Ws[DIM * F1 / 4];   // 32KB
    int tid = threadIdx.x;
    #pragma unroll
    for (int i = tid; i < DIM * F1 / 4; i += 256)
        Ws[i] = ((const float4*)W1)[i];
    __syncthreads();

    int nodeLocal = tid >> 3;     // 0..31
    int tj = tid & 7;             // channels [tj*8, tj*8+8)
    int n = blockIdx.x * 32 + nodeLocal;
    const float* xr = x + (size_t)n * DIM;

    float4 a0 = make_float4(0.f, 0.f, 0.f, 0.f);
    float4 a1 = make_float4(0.f, 0.f, 0.f, 0.f);
    #pragma unroll 4
    for (int k = 0; k < DIM; k++) {
        float xv = __ldg(xr + k);
        float4 w0 = Ws[k * 16 + tj * 2];
        float4 w1 = Ws[k * 16 + tj * 2 + 1];
        a0.x += xv * w0.x; a0.y += xv * w0.y; a0.z += xv * w0.z; a0.w += xv * w0.w;
        a1.x += xv * w1.x; a1.y += xv * w1.y; a1.z += xv * w1.z; a1.w += xv * w1.w;
    }

    float4* h1p = (float4*)(g_h1 + (size_t)n * F1 + tj * 8);
    h1p[0] = a0; h1p[1] = a1;

    int j0 = tj * 8;
    float ps = a0.x * asrc[j0]     + a0.y * asrc[j0 + 1] +
               a0.z * asrc[j0 + 2] + a0.w * asrc[j0 + 3] +
               a1.x * asrc[j0 + 4] + a1.y * asrc[j0 + 5] +
               a1.z * asrc[j0 + 6] + a1.w * asrc[j0 + 7];
    float pd = a0.x * adst[j0]     + a0.y * adst[j0 + 1] +
               a0.z * adst[j0 + 2] + a0.w * adst[j0 + 3] +
               a1.x * adst[j0 + 4] + a1.y * adst[j0 + 5] +
               a1.z * adst[j0 + 6] + a1.w * adst[j0 + 7];
    ps += __shfl_xor_sync(0xffffffffu, ps, 1);
    pd += __shfl_xor_sync(0xffffffffu, pd, 1);
    if ((tj & 1) == 0) {
        int h = tj >> 1;
        g_as1[n * HEADS + h] = ps;
        g_ad1[n * HEADS + h] = pd;
    }
}

// ---------------- CSR build ---------------------------------------------------
// count: reads only the dst half, 4 edges/thread (EE and ETOT divisible by 4)
__global__ void k_count(const int* __restrict__ ei) {
    int t = blockIdx.x * blockDim.x + threadIdx.x;
    if (t >= ETOT / 4) return;
    int e = t * 4;
    if (e < EE) {
        int4 d4 = *(const int4*)(ei + EE + e);
        atomicAdd(&g_deg[d4.x], 1);
        atomicAdd(&g_deg[d4.y], 1);
        atomicAdd(&g_deg[d4.z], 1);
        atomicAdd(&g_deg[d4.w], 1);
    } else {
        int n = e - EE;
        atomicAdd(&g_deg[n + 0], 1);
        atomicAdd(&g_deg[n + 1], 1);
        atomicAdd(&g_deg[n + 2], 1);
        atomicAdd(&g_deg[n + 3], 1);
    }
}

__global__ __launch_bounds__(SCAN_BLK) void k_scan1() {
    __shared__ int sh[SCAN_BLK];
    int t = threadIdx.x;
    int i = blockIdx.x * SCAN_BLK + t;
    int v = (i < NN) ? g_deg[i] : 0;
    sh[t] = v;
    __syncthreads();
    #pragma unroll
    for (int off = 1; off < SCAN_BLK; off <<= 1) {
        int add = (t >= off) ? sh[t - off] : 0;
        __syncthreads();
        sh[t] += add;
        __syncthreads();
    }
    if (i < NN) g_offs[i] = sh[t] - v;   // exclusive
    if (t == SCAN_BLK - 1) g_bsum[blockIdx.x] = sh[t];
}

__global__ __launch_bounds__(256) void k_scan2() {
    __shared__ int sh[256];
    int t = threadIdx.x;
    int v = (t < NBLK) ? g_bsum[t] : 0;
    sh[t] = v;
    __syncthreads();
    #pragma unroll
    for (int off = 1; off < 256; off <<= 1) {
        int add = (t >= off) ? sh[t - off] : 0;
        __syncthreads();
        sh[t] += add;
        __syncthreads();
    }
    if (t < NBLK) g_bpre[t] = sh[t] - v;  // exclusive
}

__global__ void k_scan3() {
    int i = blockIdx.x * blockDim.x + threadIdx.x;
    if (i >= NN) return;
    int o = g_offs[i] + g_bpre[i / SCAN_BLK];
    g_offs[i] = o;
    g_cur[i] = o;
}

__global__ void k_scatter(const int* __restrict__ ei) {
    int e = blockIdx.x * blockDim.x + threadIdx.x;
    if (e >= ETOT) return;
    int s, d; load_edge(ei, e, s, d);
    int pos = atomicAdd(&g_cur[d], 1);
    g_csr_src[pos] = s;
}

// ---------------- layer-1 aggregation (atomic-free) + fused l2prep ------------
// One warp per dst node. Lane owns channels (2*lane, 2*lane+1); head = lane>>3.
__global__ __launch_bounds__(256) void k_agg1(
    const float* __restrict__ b1, const float* __restrict__ W2,
    const float* __restrict__ as2, const float* __restrict__ ad2) {

    int lane = threadIdx.x & 31;
    int n = blockIdx.x * 8 + (threadIdx.x >> 5);
    if (n >= NN) return;

    int h = lane >> 3;
    float adh = g_ad1[n * 4 + h];
    int start = g_offs[n];
    int end = start + g_deg[n];
    int c = 2 * lane;

    float acc0 = 0.f, acc1 = 0.f, wsum = 0.f;
    int i = start;
    for (; i + 4 <= end; i += 4) {
        int s0 = __ldg(g_csr_src + i + 0);
        int s1 = __ldg(g_csr_src + i + 1);
        int s2 = __ldg(g_csr_src + i + 2);
        int s3 = __ldg(g_csr_src + i + 3);
        float e0 = __ldg(g_as1 + s0 * 4 + h);
        float e1 = __ldg(g_as1 + s1 * 4 + h);
        float e2 = __ldg(g_as1 + s2 * 4 + h);
        float e3 = __ldg(g_as1 + s3 * 4 + h);
        float2 q0 = *(const float2*)(g_h1 + (size_t)s0 * F1 + c);
        float2 q1 = *(const float2*)(g_h1 + (size_t)s1 * F1 + c);
        float2 q2 = *(const float2*)(g_h1 + (size_t)s2 * F1 + c);
        float2 q3 = *(const float2*)(g_h1 + (size_t)s3 * F1 + c);
        float w0 = __expf(lrelu(e0 + adh));
        float w1 = __expf(lrelu(e1 + adh));
        float w2 = __expf(lrelu(e2 + adh));
        float w3 = __expf(lrelu(e3 + adh));
        acc0 += w0 * q0.x + w1 * q1.x;
        acc1 += w0 * q0.y + w1 * q1.y;
        acc0 += w2 * q2.x + w3 * q3.x;
        acc1 += w2 * q2.y + w3 * q3.y;
        wsum += (w0 + w1) + (w2 + w3);
    }
    for (; i < end; i++) {
        int s = __ldg(g_csr_src + i);
        float as = __ldg(g_as1 + s * 4 + h);
        float w = __expf(lrelu(as + adh));
        float2 hv = *(const float2*)(g_h1 + (size_t)s * F1 + c);
        acc0 += w * hv.x;
        acc1 += w * hv.y;
        wsum += w;
    }

    float inv = 1.0f / (wsum + 1e-16f);
    int c0 = c, c1 = c + 1;
    float v0 = acc0 * inv + b1[c0];
    float v1 = acc1 * inv + b1[c1];
    v0 = v0 > 0.f ? v0 : expm1f(v0);          // ELU
    v1 = v1 > 0.f ? v1 : expm1f(v1);

    float p0 = v0 * W2[c0 * 2 + 0] + v1 * W2[c1 * 2 + 0];
    float p1 = v0 * W2[c0 * 2 + 1] + v1 * W2[c1 * 2 + 1];
    #pragma unroll
    for (int o = 16; o > 0; o >>= 1) {
        p0 += __shfl_down_sync(0xffffffffu, p0, o);
        p1 += __shfl_down_sync(0xffffffffu, p1, o);
    }
    if (lane == 0) {
        g_h3[n * 2 + 0] = p0;
        g_h3[n * 2 + 1] = p1;
        g_as2[n] = p0 * as2[0] + p1 * as2[1];
        g_ad2[n] = p0 * ad2[0] + p1 * ad2[1];
    }
}

// ---------------- layer-2 aggregation (atomic-free) + output ------------------
__global__ __launch_bounds__(256) void k_agg2(
    float* __restrict__ out, const float* __restrict__ b2) {

    int lane = threadIdx.x & 31;
    int n = blockIdx.x * 8 + (threadIdx.x >> 5);
    if (n >= NN) return;

    float ad = g_ad2[n];
    int start = g_offs[n];
    int end = start + g_deg[n];

    float a0 = 0.f, a1 = 0.f, wsum = 0.f;
    for (int i = start + lane; i < end; i += 32) {
        int s = __ldg(g_csr_src + i);
        float w = __expf(lrelu(__ldg(g_as2 + s) + ad));
        float2 hv = *(const float2*)(g_h3 + s * 2);
        a0 += w * hv.x;
        a1 += w * hv.y;
        wsum += w;
    }
    #pragma unroll
    for (int o = 16; o > 0; o >>= 1) {
        a0   += __shfl_down_sync(0xffffffffu, a0, o);
        a1   += __shfl_down_sync(0xffffffffu, a1, o);
        wsum += __shfl_down_sync(0xffffffffu, wsum, o);
    }
    if (lane == 0) {
        float inv = 1.0f / (wsum + 1e-16f);
        out[n * 2 + 0] = a0 * inv + b2[0];
        out[n * 2 + 1] = a1 * inv + b2[1];
    }
}

// ---------------- launch ------------------------------------------------------
extern "C" void kernel_launch(void* const* d_in, const int* in_sizes, int n_in,
                              void* d_out, int out_size) {
    const float* x    = (const float*)d_in[0];
    const int*   ei   = (const int*)  d_in[1];
    const float* W1   = (const float*)d_in[2];
    const float* as1  = (const float*)d_in[3];
    const float* ad1  = (const float*)d_in[4];
    const float* b1   = (const float*)d_in[5];
    const float* W2   = (const float*)d_in[6];
    const float* as2  = (const float*)d_in[7];
    const float* ad2  = (const float*)d_in[8];
    const float* b2   = (const float*)d_in[9];
    float* out = (float*)d_out;

    // One-time host-side resources (host objects only; no device allocation).
    static cudaStream_t s2 = nullptr;
    static cudaEvent_t evFork = nullptr, evJoin = nullptr;
    if (!s2) {
        cudaStreamCreateWithFlags(&s2, cudaStreamNonBlocking);
        cudaEventCreateWithFlags(&evFork, cudaEventDisableTiming);
        cudaEventCreateWithFlags(&evJoin, cudaEventDisableTiming);
    }

    const int T = 256;

    // Fork: CSR build chain (depends only on ei) runs on s2, concurrent with
    // the feature GEMM (depends only on x/W1) on the main stream.
    cudaEventRecord(evFork, 0);
    cudaStreamWaitEvent(s2, evFork, 0);

    k_gemm1<<<NN / 32, T>>>(x, W1, as1, ad1);          // main stream

    k_init<<<(NN + T - 1) / T, T, 0, s2>>>();
    k_count<<<(ETOT / 4 + T - 1) / T, T, 0, s2>>>(ei);
    k_scan1<<<NBLK, SCAN_BLK, 0, s2>>>();
    k_scan2<<<1, 256, 0, s2>>>();
    k_scan3<<<(NN + T - 1) / T, T, 0, s2>>>();
    k_scatter<<<(ETOT + T - 1) / T, T, 0, s2>>>(ei);

    // Join
    cudaEventRecord(evJoin, s2);
    cudaStreamWaitEvent(0, evJoin, 0);

    k_agg1<<<(NN + 7) / 8, T>>>(b1, W2, as2, ad2);
    k_agg2<<<(NN + 7) / 8, T>>>(out, b2);
}